// round 5
// baseline (speedup 1.0000x reference)
#include <cuda_runtime.h>

#define D 128
#define NMAX 50176
#define EMAX 800000
#define N_LAYERS 4

// Scratch (device globals: allocation-free rule)
__device__ int   g_deg_out[NMAX];
__device__ int   g_deg_in[NMAX];
__device__ float g_norm_src[NMAX];
__device__ float g_norm_dst[NMAX];
__device__ int   g_row_ptr[NMAX + 1];
__device__ int   g_cursor[NMAX];
__device__ int   g_col[EMAX];
__device__ __align__(16) float g_h0[NMAX * D];
__device__ __align__(16) float g_h1[NMAX * D];
__device__ __align__(16) float g_agg[NMAX * D];

__global__ void k_count(const int* __restrict__ src,
                        const int* __restrict__ dst, int e) {
    int i = blockIdx.x * blockDim.x + threadIdx.x;
    if (i < e) {
        atomicAdd(&g_deg_out[src[i]], 1);
        atomicAdd(&g_deg_in[dst[i]], 1);
    }
}

__global__ void k_norm(int n) {
    int i = blockIdx.x * blockDim.x + threadIdx.x;
    if (i < n) {
        g_norm_src[i] = rsqrtf(fmaxf((float)g_deg_out[i], 1.0f));
        g_norm_dst[i] = rsqrtf(fmaxf((float)g_deg_in[i], 1.0f));
    }
}

// Single-block exclusive scan of g_deg_in -> g_row_ptr / g_cursor.
// 1024 threads; each thread serially owns a contiguous chunk, partials are
// scanned with warp shuffles (2 levels, 3 barriers total).
__global__ void k_scan(int n) {
    __shared__ int warp_sums[32];
    int t    = threadIdx.x;
    int lane = t & 31;
    int wid  = t >> 5;
    int chunk = (n + 1023) >> 10;           // ceil(n/1024)
    int start = t * chunk;
    int end   = min(start + chunk, n);

    int local = 0;
    for (int i = start; i < end; i++) local += g_deg_in[i];

    // warp inclusive scan
    int x = local;
    #pragma unroll
    for (int off = 1; off < 32; off <<= 1) {
        int y = __shfl_up_sync(0xffffffffu, x, off);
        if (lane >= off) x += y;
    }
    if (lane == 31) warp_sums[wid] = x;
    __syncthreads();
    if (wid == 0) {
        int s = warp_sums[lane];
        #pragma unroll
        for (int off = 1; off < 32; off <<= 1) {
            int y = __shfl_up_sync(0xffffffffu, s, off);
            if (lane >= off) s += y;
        }
        warp_sums[lane] = s;                // inclusive warp totals
    }
    __syncthreads();

    int excl = x - local + (wid > 0 ? warp_sums[wid - 1] : 0);
    int run = excl;
    for (int i = start; i < end; i++) {
        int v = g_deg_in[i];
        g_row_ptr[i] = run;
        g_cursor[i]  = run;
        run += v;
    }
    if (t == 0) g_row_ptr[n] = warp_sums[31];
}

__global__ void k_fill(const int* __restrict__ src,
                       const int* __restrict__ dst, int e) {
    int i = blockIdx.x * blockDim.x + threadIdx.x;
    if (i < e) {
        int p = atomicAdd(&g_cursor[dst[i]], 1);
        g_col[p] = src[i];
    }
}

// Aggregation: one warp per destination node, lane = one float4 (4 of 128 dims)
// agg[i] = norm_dst[i] * sum_{s in in(i)} norm_src[s] * h[s]
__global__ void k_agg(const float* __restrict__ hin, float* __restrict__ agg, int n) {
    int w    = (blockIdx.x * blockDim.x + threadIdx.x) >> 5;
    int lane = threadIdx.x & 31;
    if (w >= n) return;
    int j0 = g_row_ptr[w];
    int j1 = g_row_ptr[w + 1];
    const float4* h4 = (const float4*)hin;
    float4 acc = make_float4(0.f, 0.f, 0.f, 0.f);
    for (int j = j0; j < j1; j++) {
        int s = g_col[j];
        float ns = g_norm_src[s];
        float4 v = __ldg(&h4[(size_t)s * 32 + lane]);
        acc.x = fmaf(ns, v.x, acc.x);
        acc.y = fmaf(ns, v.y, acc.y);
        acc.z = fmaf(ns, v.z, acc.z);
        acc.w = fmaf(ns, v.w, acc.w);
    }
    float nd = g_norm_dst[w];
    float4 o = make_float4(acc.x * nd, acc.y * nd, acc.z * nd, acc.w * nd);
    ((float4*)agg)[(size_t)w * 32 + lane] = o;
}

// C[n,128] = A[n,128] @ Wl[128,128] + bl[128]
// Block tile 64(M) x 128(N full), K chunked by 32. 256 threads, 8x4 micro-tile.
__global__ void k_gemm(const float* __restrict__ A, const float* __restrict__ Wl,
                       const float* __restrict__ bl, float* __restrict__ C, int n) {
    __shared__ __align__(16) float As[32][68];   // transposed A chunk, padded row
    __shared__ float4 Ws[32][32];                // W chunk [k][n/4]
    int tid = threadIdx.x;
    int tx = tid & 31;       // n4 index: cols tx*4 .. tx*4+3
    int ty = tid >> 5;       // m group: rows ty*8 .. ty*8+7
    int m0 = blockIdx.x * 64;
    float acc[8][4] = {};
    const float4* W4 = (const float4*)Wl;

    for (int kc = 0; kc < 128; kc += 32) {
        // A tile: rows m0..m0+63, cols kc..kc+31 -> As[k][m] (transposed)
        #pragma unroll
        for (int it = 0; it < 2; it++) {
            int m = (tid >> 3) + it * 32;
            int c4 = tid & 7;
            int row = m0 + m;
            float4 v = make_float4(0.f, 0.f, 0.f, 0.f);
            if (row < n) v = *(const float4*)&A[(size_t)row * 128 + kc + c4 * 4];
            As[c4 * 4 + 0][m] = v.x;
            As[c4 * 4 + 1][m] = v.y;
            As[c4 * 4 + 2][m] = v.z;
            As[c4 * 4 + 3][m] = v.w;
        }
        // W chunk: 32 k-rows x 128 cols = 1024 float4
        #pragma unroll
        for (int it = 0; it < 4; it++) {
            int idx = tid + it * 256;
            int k  = idx >> 5;
            int n4 = idx & 31;
            Ws[k][n4] = W4[(size_t)(kc + k) * 32 + n4];
        }
        __syncthreads();
        #pragma unroll
        for (int k = 0; k < 32; k++) {
            float4 w  = Ws[k][tx];
            float4 a0 = *(const float4*)&As[k][ty * 8];
            float4 a1 = *(const float4*)&As[k][ty * 8 + 4];
            float av[8] = {a0.x, a0.y, a0.z, a0.w, a1.x, a1.y, a1.z, a1.w};
            #pragma unroll
            for (int i = 0; i < 8; i++) {
                acc[i][0] = fmaf(av[i], w.x, acc[i][0]);
                acc[i][1] = fmaf(av[i], w.y, acc[i][1]);
                acc[i][2] = fmaf(av[i], w.z, acc[i][2]);
                acc[i][3] = fmaf(av[i], w.w, acc[i][3]);
            }
        }
        __syncthreads();
    }

    float4 bb = ((const float4*)bl)[tx];
    #pragma unroll
    for (int i = 0; i < 8; i++) {
        int row = m0 + ty * 8 + i;
        if (row < n) {
            float4 o = make_float4(acc[i][0] + bb.x, acc[i][1] + bb.y,
                                   acc[i][2] + bb.z, acc[i][3] + bb.w);
            ((float4*)C)[(size_t)row * 32 + tx] = o;
        }
    }
}

extern "C" void kernel_launch(void* const* d_in, const int* in_sizes, int n_in,
                              void* d_out, int out_size) {
    const float* feat = (const float*)d_in[0];
    const float* W    = (const float*)d_in[1];
    const float* b    = (const float*)d_in[2];
    const int*   src  = (const int*)d_in[3];   // jax default x64 off: int32 arrays
    const int*   dst  = (const int*)d_in[4];
    int N = in_sizes[0] / D;
    int E = in_sizes[3];

    float *h0, *h1, *agg;
    cudaGetSymbolAddress((void**)&h0,  g_h0);
    cudaGetSymbolAddress((void**)&h1,  g_h1);
    cudaGetSymbolAddress((void**)&agg, g_agg);

    int* deg_out_p;
    int* deg_in_p;
    cudaGetSymbolAddress((void**)&deg_out_p, g_deg_out);
    cudaGetSymbolAddress((void**)&deg_in_p,  g_deg_in);
    cudaMemsetAsync(deg_out_p, 0, (size_t)N * sizeof(int));
    cudaMemsetAsync(deg_in_p,  0, (size_t)N * sizeof(int));

    int nb = (N + 255) / 256;
    int eb = (E + 255) / 256;

    // Setup: degrees, norms, CSR by dst
    k_count<<<eb, 256>>>(src, dst, E);
    k_norm<<<nb, 256>>>(N);
    k_scan<<<1, 1024>>>(N);
    k_fill<<<eb, 256>>>(src, dst, E);

    float* out = (float*)d_out;
    const float* hin = feat;
    int aggBlocks  = (N + 7) / 8;       // 8 warps per block, warp per node
    int gemmBlocks = (N + 63) / 64;

    for (int l = 0; l < N_LAYERS; l++) {
        k_agg<<<aggBlocks, 256>>>(hin, agg, N);
        float* hout = (l == N_LAYERS - 1) ? out : ((l & 1) ? h1 : h0);
        k_gemm<<<gemmBlocks, 256>>>(agg, W + (size_t)l * D * D, b + (size_t)l * D, hout, N);
        hin = hout;
    }
}

// round 7
// speedup vs baseline: 1.1671x; 1.1671x over previous
#include <cuda_runtime.h>
#include <cuda_bf16.h>
#include <cstdint>

#define D 128
#define NMAX 50176
#define EMAX 800000
#define N_LAYERS 4

// ---------------- device scratch (allocation-free rule) ----------------
__device__ int   g_deg_out[NMAX];
__device__ int   g_deg_in[NMAX];
__device__ float g_norm_src[NMAX];
__device__ float g_norm_dst[NMAX];
__device__ int   g_row_ptr[NMAX + 1];
__device__ int   g_cursor[NMAX];
__device__ int   g_col[EMAX];
__device__ __align__(16) float    g_h0[NMAX * D];
__device__ __align__(16) float    g_h1[NMAX * D];
// Aggregated features as packed bf16 pairs (hi/lo split), 64 pairs per node
__device__ __align__(16) uint32_t g_agg_hi[NMAX * 64];
__device__ __align__(16) uint32_t g_agg_lo[NMAX * 64];
// W in mma-fragment layout: [layer][kstep(8)][nfrag(16)][lane(32)] = {hi0,hi1,lo0,lo1}
__device__ __align__(16) uint4    g_wfrag[N_LAYERS * 8 * 16 * 32];

// ---------------- setup kernels ----------------
__global__ void k_count(const int* __restrict__ src, const int* __restrict__ dst, int e) {
    int i = blockIdx.x * blockDim.x + threadIdx.x;
    if (i < e) {
        atomicAdd(&g_deg_out[src[i]], 1);
        atomicAdd(&g_deg_in[dst[i]], 1);
    }
}

__global__ void k_norm(int n) {
    int i = blockIdx.x * blockDim.x + threadIdx.x;
    if (i < n) {
        g_norm_src[i] = rsqrtf(fmaxf((float)g_deg_out[i], 1.0f));
        g_norm_dst[i] = rsqrtf(fmaxf((float)g_deg_in[i], 1.0f));
    }
}

__global__ void k_scan(int n) {
    __shared__ int warp_sums[32];
    int t = threadIdx.x, lane = t & 31, wid = t >> 5;
    int chunk = (n + 1023) >> 10;
    int start = t * chunk;
    int end = min(start + chunk, n);
    int local = 0;
    for (int i = start; i < end; i++) local += g_deg_in[i];
    int x = local;
    #pragma unroll
    for (int off = 1; off < 32; off <<= 1) {
        int y = __shfl_up_sync(0xffffffffu, x, off);
        if (lane >= off) x += y;
    }
    if (lane == 31) warp_sums[wid] = x;
    __syncthreads();
    if (wid == 0) {
        int s = warp_sums[lane];
        #pragma unroll
        for (int off = 1; off < 32; off <<= 1) {
            int y = __shfl_up_sync(0xffffffffu, s, off);
            if (lane >= off) s += y;
        }
        warp_sums[lane] = s;
    }
    __syncthreads();
    int run = x - local + (wid > 0 ? warp_sums[wid - 1] : 0);
    for (int i = start; i < end; i++) {
        int v = g_deg_in[i];
        g_row_ptr[i] = run;
        g_cursor[i] = run;
        run += v;
    }
    if (t == 0) g_row_ptr[n] = warp_sums[31];
}

__global__ void k_fill(const int* __restrict__ src, const int* __restrict__ dst, int e) {
    int i = blockIdx.x * blockDim.x + threadIdx.x;
    if (i < e) {
        int p = atomicAdd(&g_cursor[dst[i]], 1);
        g_col[p] = src[i];
    }
}

// Build W fragments: B operand (K x N col-frag) for mma.m16n8k16.
// reg0 = rows k0+(lane%4)*2,+1 at col c; reg1 = +8 rows. hi/lo bf16 split.
__global__ void k_prep_w(const float* __restrict__ W) {
    int idx = blockIdx.x * blockDim.x + threadIdx.x;   // 4*8*16*32 = 16384
    if (idx >= N_LAYERS * 8 * 16 * 32) return;
    int lane = idx & 31;
    int nfg  = (idx >> 5) & 15;
    int ks   = (idx >> 9) & 7;
    int l    = idx >> 12;
    int c  = nfg * 8 + (lane >> 2);
    int rk = ks * 16 + (lane & 3) * 2;
    const float* Wl = W + (size_t)l * D * D;
    float w00 = Wl[rk * D + c];
    float w01 = Wl[(rk + 1) * D + c];
    float w10 = Wl[(rk + 8) * D + c];
    float w11 = Wl[(rk + 9) * D + c];
    __nv_bfloat162 h, lo;
    uint4 out;
    h.x = __float2bfloat16_rn(w00); h.y = __float2bfloat16_rn(w01);
    lo.x = __float2bfloat16_rn(w00 - __bfloat162float(h.x));
    lo.y = __float2bfloat16_rn(w01 - __bfloat162float(h.y));
    out.x = *(uint32_t*)&h;
    out.z = *(uint32_t*)&lo;
    h.x = __float2bfloat16_rn(w10); h.y = __float2bfloat16_rn(w11);
    lo.x = __float2bfloat16_rn(w10 - __bfloat162float(h.x));
    lo.y = __float2bfloat16_rn(w11 - __bfloat162float(h.y));
    out.y = *(uint32_t*)&h;
    out.w = *(uint32_t*)&lo;
    g_wfrag[((size_t)l * 128 + ks * 16 + nfg) * 32 + lane] = out;
}

// ---------------- aggregation: warp per node, writes bf16 hi/lo pairs ----------------
__global__ void k_agg(const float* __restrict__ hin, int n) {
    int w = (blockIdx.x * blockDim.x + threadIdx.x) >> 5;
    int lane = threadIdx.x & 31;
    if (w >= n) return;
    int j0 = g_row_ptr[w];
    int j1 = g_row_ptr[w + 1];
    const float4* h4 = (const float4*)hin;
    float4 acc = make_float4(0.f, 0.f, 0.f, 0.f);
    for (int j = j0; j < j1; j++) {
        int s = g_col[j];
        float ns = g_norm_src[s];
        float4 v = __ldg(&h4[(size_t)s * 32 + lane]);
        acc.x = fmaf(ns, v.x, acc.x);
        acc.y = fmaf(ns, v.y, acc.y);
        acc.z = fmaf(ns, v.z, acc.z);
        acc.w = fmaf(ns, v.w, acc.w);
    }
    float nd = g_norm_dst[w];
    float ox = acc.x * nd, oy = acc.y * nd, oz = acc.z * nd, ow = acc.w * nd;
    __nv_bfloat162 h01, h23, l01, l23;
    h01.x = __float2bfloat16_rn(ox); h01.y = __float2bfloat16_rn(oy);
    h23.x = __float2bfloat16_rn(oz); h23.y = __float2bfloat16_rn(ow);
    l01.x = __float2bfloat16_rn(ox - __bfloat162float(h01.x));
    l01.y = __float2bfloat16_rn(oy - __bfloat162float(h01.y));
    l23.x = __float2bfloat16_rn(oz - __bfloat162float(h23.x));
    l23.y = __float2bfloat16_rn(ow - __bfloat162float(h23.y));
    uint2 ph, pl;
    ph.x = *(uint32_t*)&h01; ph.y = *(uint32_t*)&h23;
    pl.x = *(uint32_t*)&l01; pl.y = *(uint32_t*)&l23;
    ((uint2*)g_agg_hi)[(size_t)w * 32 + lane] = ph;
    ((uint2*)g_agg_lo)[(size_t)w * 32 + lane] = pl;
}

// ---------------- GEMM via mma.sync bf16 (hi/lo split) ----------------
__device__ __forceinline__ void mma16816(float* d, const uint32_t* a, uint32_t b0, uint32_t b1) {
    asm volatile(
        "mma.sync.aligned.m16n8k16.row.col.f32.bf16.bf16.f32 "
        "{%0,%1,%2,%3}, {%4,%5,%6,%7}, {%8,%9}, {%0,%1,%2,%3};"
        : "+f"(d[0]), "+f"(d[1]), "+f"(d[2]), "+f"(d[3])
        : "r"(a[0]), "r"(a[1]), "r"(a[2]), "r"(a[3]), "r"(b0), "r"(b1));
}

// CTA: 128 rows x 128 cols. 8 warps: 4 (M, 32 rows each) x 2 (N, 64 cols each).
__global__ void __launch_bounds__(256)
k_gemm_mma(const uint4* __restrict__ wfrag, const float* __restrict__ bias,
           float* __restrict__ C, int n) {
    int tid = threadIdx.x;
    int warp = tid >> 5, lane = tid & 31;
    int warp_m = warp & 3, warp_n = warp >> 2;
    int m_base = blockIdx.x * 128 + warp_m * 32;
    int n_base = warp_n * 64;
    int r0 = lane >> 2;          // 0..7
    int cp = lane & 3;           // col-pair index within fragment

    float d[2][8][4];
    #pragma unroll
    for (int mf = 0; mf < 2; mf++)
        #pragma unroll
        for (int nf = 0; nf < 8; nf++)
            #pragma unroll
            for (int j = 0; j < 4; j++) d[mf][nf][j] = 0.f;

    #pragma unroll
    for (int ks = 0; ks < 8; ks++) {
        int p0 = ks * 8 + cp;    // pair index: k0/2 + cp  (k0 = ks*16)
        uint32_t ah[2][4], al[2][4];
        #pragma unroll
        for (int mf = 0; mf < 2; mf++) {
            int row0 = m_base + mf * 16 + r0;
            int row1 = row0 + 8;
            bool v0 = row0 < n, v1 = row1 < n;
            size_t b0 = (size_t)row0 * 64 + p0;
            size_t b1 = (size_t)row1 * 64 + p0;
            ah[mf][0] = v0 ? g_agg_hi[b0]     : 0u;
            ah[mf][1] = v1 ? g_agg_hi[b1]     : 0u;
            ah[mf][2] = v0 ? g_agg_hi[b0 + 4] : 0u;
            ah[mf][3] = v1 ? g_agg_hi[b1 + 4] : 0u;
            al[mf][0] = v0 ? g_agg_lo[b0]     : 0u;
            al[mf][1] = v1 ? g_agg_lo[b1]     : 0u;
            al[mf][2] = v0 ? g_agg_lo[b0 + 4] : 0u;
            al[mf][3] = v1 ? g_agg_lo[b1 + 4] : 0u;
        }
        #pragma unroll
        for (int nf = 0; nf < 8; nf++) {
            uint4 w = wfrag[((size_t)ks * 16 + warp_n * 8 + nf) * 32 + lane];
            #pragma unroll
            for (int mf = 0; mf < 2; mf++) {
                mma16816(d[mf][nf], ah[mf], w.x, w.y);   // hi * hi
                mma16816(d[mf][nf], ah[mf], w.z, w.w);   // hi * lo
                mma16816(d[mf][nf], al[mf], w.x, w.y);   // lo * hi
            }
        }
    }

    // Epilogue: bias add + store
    #pragma unroll
    for (int nf = 0; nf < 8; nf++) {
        int col = n_base + nf * 8 + cp * 2;
        float2 bb = *(const float2*)&bias[col];
        #pragma unroll
        for (int mf = 0; mf < 2; mf++) {
            int row0 = m_base + mf * 16 + r0;
            int row1 = row0 + 8;
            if (row0 < n) {
                float2 o = make_float2(d[mf][nf][0] + bb.x, d[mf][nf][1] + bb.y);
                *(float2*)&C[(size_t)row0 * 128 + col] = o;
            }
            if (row1 < n) {
                float2 o = make_float2(d[mf][nf][2] + bb.x, d[mf][nf][3] + bb.y);
                *(float2*)&C[(size_t)row1 * 128 + col] = o;
            }
        }
    }
}

// ---------------- host ----------------
extern "C" void kernel_launch(void* const* d_in, const int* in_sizes, int n_in,
                              void* d_out, int out_size) {
    const float* feat = (const float*)d_in[0];
    const float* W    = (const float*)d_in[1];
    const float* b    = (const float*)d_in[2];
    const int*   src  = (const int*)d_in[3];   // jax x64-off: int32
    const int*   dst  = (const int*)d_in[4];
    int N = in_sizes[0] / D;
    int E = in_sizes[3];

    float *h0, *h1;
    cudaGetSymbolAddress((void**)&h0, g_h0);
    cudaGetSymbolAddress((void**)&h1, g_h1);
    uint4* wfrag;
    cudaGetSymbolAddress((void**)&wfrag, g_wfrag);
    int* deg_out_p; int* deg_in_p;
    cudaGetSymbolAddress((void**)&deg_out_p, g_deg_out);
    cudaGetSymbolAddress((void**)&deg_in_p,  g_deg_in);
    cudaMemsetAsync(deg_out_p, 0, (size_t)N * sizeof(int));
    cudaMemsetAsync(deg_in_p,  0, (size_t)N * sizeof(int));

    int nb = (N + 255) / 256;
    int eb = (E + 255) / 256;

    k_count<<<eb, 256>>>(src, dst, E);
    k_norm<<<nb, 256>>>(N);
    k_scan<<<1, 1024>>>(N);
    k_fill<<<eb, 256>>>(src, dst, E);
    k_prep_w<<<(N_LAYERS * 8 * 16 * 32 + 255) / 256, 256>>>(W);

    float* out = (float*)d_out;
    const float* hin = feat;
    int aggBlocks  = (N + 7) / 8;
    int gemmBlocks = (N + 127) / 128;

    for (int l = 0; l < N_LAYERS; l++) {
        k_agg<<<aggBlocks, 256>>>(hin, N);
        float* hout = (l == N_LAYERS - 1) ? out : ((l & 1) ? h1 : h0);
        k_gemm_mma<<<gemmBlocks, 256>>>(wfrag + (size_t)l * 128 * 32,
                                        b + (size_t)l * D, hout, N);
        hin = hout;
    }
}